// round 1
// baseline (speedup 1.0000x reference)
#include <cuda_runtime.h>

#define LEAK 0.8f
#define TH   0.5f

// Precomputed recurrent-matvec lookup tables (binary spike vectors -> dot products).
// table1[m][j] = sum_i ((m>>i)&1) * W_hh[j][i]   (bias added separately, matching
//                the reference's (LEAK*m2 + dot) + b_hh association)
// table2[m]   = sum_j ((m>>j)&1) * W_ho[0][j]
__device__ float g_t1[256 * 8];
__device__ float g_t2[256];

__global__ void build_tables(const float* __restrict__ W_hh,
                             const float* __restrict__ W_ho) {
    int m = threadIdx.x;  // 0..255
#pragma unroll
    for (int j = 0; j < 8; j++) {
        float s = 0.f;
#pragma unroll
        for (int i = 0; i < 8; i++)
            if ((m >> i) & 1) s = __fadd_rn(s, W_hh[j * 8 + i]);
        g_t1[m * 8 + j] = s;
    }
    float s2 = 0.f;
#pragma unroll
    for (int j = 0; j < 8; j++)
        if ((m >> j) & 1) s2 = __fadd_rn(s2, W_ho[j]);
    g_t2[m] = s2;
}

__global__ __launch_bounds__(256) void snn_kernel(
    const float* __restrict__ x,
    const float* __restrict__ W_ih,
    const float* __restrict__ b_ih,
    const float* __restrict__ b_hh,
    const float* __restrict__ b_ho,
    float* __restrict__ out,
    int B)
{
    __shared__ float4 sT1[512];   // table1 as float4 pairs: sT1[2m], sT1[2m+1]
    __shared__ float  sT2[256];

    int tid = threadIdx.x;
    const float4* gt1 = reinterpret_cast<const float4*>(g_t1);
    for (int i = tid; i < 512; i += 256) sT1[i] = gt1[i];
    sT2[tid] = g_t2[tid];
    __syncthreads();

    // Broadcast-load small parameter vectors into registers (uniform addresses,
    // single L1 transaction per load after warm-up).
    float wih[16], bi[8], bh[8];
#pragma unroll
    for (int j = 0; j < 16; j++) wih[j] = W_ih[j];
#pragma unroll
    for (int j = 0; j < 8; j++)  bi[j]  = b_ih[j];
#pragma unroll
    for (int j = 0; j < 8; j++)  bh[j]  = b_hh[j];
    float bo = b_ho[0];

    int idx = blockIdx.x * 256 + tid;
    if (idx >= B) return;

    float2 xv = reinterpret_cast<const float2*>(x)[idx];

    // Input current: identical every step. Strict left-to-right association:
    // (x0*w0 + x1*w1) + b
    float cur[8];
#pragma unroll
    for (int j = 0; j < 8; j++)
        cur[j] = __fadd_rn(
            __fadd_rn(__fmul_rn(xv.x, wih[2 * j]),
                      __fmul_rn(xv.y, wih[2 * j + 1])),
            bi[j]);

    float m1[8], m2[8];
#pragma unroll
    for (int j = 0; j < 8; j++) { m1[j] = 0.f; m2[j] = 0.f; }
    float mo = 0.f, cnt = 0.f;

#pragma unroll
    for (int t = 0; t < 16; t++) {
        // Layer 1: per-channel LIF, build 8-bit spike mask.
        unsigned mask1 = 0;
#pragma unroll
        for (int j = 0; j < 8; j++) {
            float v = __fadd_rn(__fmul_rn(LEAK, m1[j]), cur[j]);
            bool s = (v >= TH);
            mask1 |= s ? (1u << j) : 0u;
            m1[j] = s ? 0.f : v;
        }

        // Layer 2: recurrent matvec via 256-entry table (2x LDS.128).
        float4 a = sT1[2 * mask1];
        float4 b = sT1[2 * mask1 + 1];
        float tt[8] = {a.x, a.y, a.z, a.w, b.x, b.y, b.z, b.w};
        unsigned mask2 = 0;
#pragma unroll
        for (int j = 0; j < 8; j++) {
            // ((LEAK*m2) + dot) + b_hh  — matches reference association
            float v = __fadd_rn(__fadd_rn(__fmul_rn(LEAK, m2[j]), tt[j]), bh[j]);
            bool s = (v >= TH);
            mask2 |= s ? (1u << j) : 0u;
            m2[j] = s ? 0.f : v;
        }

        // Output layer: scalar LIF via 256-entry table (1x LDS.32).
        float v = __fadd_rn(__fadd_rn(__fmul_rn(LEAK, mo), sT2[mask2]), bo);
        bool s = (v >= TH);
        cnt += s ? 1.f : 0.f;
        mo = s ? 0.f : v;
    }

    out[idx] = cnt * 0.0625f;  // /16 exact (power of 2)
}

extern "C" void kernel_launch(void* const* d_in, const int* in_sizes, int n_in,
                              void* d_out, int out_size) {
    const float* x    = (const float*)d_in[0];
    const float* W_ih = (const float*)d_in[1];
    const float* b_ih = (const float*)d_in[2];
    const float* W_hh = (const float*)d_in[3];
    const float* b_hh = (const float*)d_in[4];
    const float* W_ho = (const float*)d_in[5];
    const float* b_ho = (const float*)d_in[6];

    int B = in_sizes[0] / 2;

    build_tables<<<1, 256>>>(W_hh, W_ho);
    snn_kernel<<<(B + 255) / 256, 256>>>(x, W_ih, b_ih, b_hh, b_ho,
                                         (float*)d_out, B);
}